// round 4
// baseline (speedup 1.0000x reference)
#include <cuda_runtime.h>

// Problem constants (fixed by the reference)
#define NN 20000
#define EE 320000
#define ET (NN + EE)          // edges incl. self loops = 340000
#define HEADS 8

// ---------------- scratch (device globals: no allocation allowed) ----------
__device__ float g_feat[(size_t)NN * 1024];   // transformed features (max layer2: N x 1024)
__device__ float g_accb[(size_t)NN * 256];    // aggregation accumulator
__device__ float g_act0[(size_t)NN * 256];    // activation after layer 0
__device__ float g_act1[(size_t)NN * 256];    // activation after layer 1
__device__ float g_resb[(size_t)NN * 256];    // residual projection
__device__ float g_als[NN * HEADS];
__device__ float g_ald[NN * HEADS];
__device__ float g_den[NN * HEADS];
__device__ unsigned g_max[NN * HEADS];
__device__ int g_src[ET];
__device__ int g_dst[ET];
__device__ int g_is64;

// Ordered-uint encoding of float for atomicMax over signed floats
__device__ __forceinline__ unsigned fenc(float f) {
    unsigned u = __float_as_uint(f);
    return (u & 0x80000000u) ? ~u : (u | 0x80000000u);
}
__device__ __forceinline__ float fdec(unsigned u) {
    return (u & 0x80000000u) ? __uint_as_float(u ^ 0x80000000u)
                             : __uint_as_float(~u);
}

// ---------------- dtype detection: int64 vs int32 edge_index ---------------
// If data is little-endian int64 with values in [0, NN), every odd 32-bit
// word of the first 4096 words is 0. With int32 data the odd words are
// random edge ids — all-zero probability is negligible.
__global__ void detect_kernel(const int* __restrict__ raw) {
    __shared__ int any;
    if (threadIdx.x == 0) any = 0;
    __syncthreads();
    for (int i = threadIdx.x; i < 2048; i += blockDim.x)
        if (raw[2 * i + 1] != 0) any = 1;
    __syncthreads();
    if (threadIdx.x == 0) g_is64 = (any == 0);
}

// ---------------- edge list build (append self loops) ----------------------
__global__ void build_edges_kernel(const void* __restrict__ eiraw) {
    int i = blockIdx.x * blockDim.x + threadIdx.x;
    if (i >= ET) return;
    int s, d;
    if (i < EE) {
        if (g_is64) {
            const long long* e = (const long long*)eiraw;
            s = (int)e[i];
            d = (int)e[EE + i];
        } else {
            const int* e = (const int*)eiraw;
            s = e[i];
            d = e[EE + i];
        }
        // clamp: a wrong dtype guess becomes rel_err, never a crash
        s = min(max(s, 0), NN - 1);
        d = min(max(d, 0), NN - 1);
    } else {
        s = d = i - EE;   // self loop
    }
    g_src[i] = s;
    g_dst[i] = d;
}

// ---------------- per-layer init: zero acc, reset max/denom ----------------
__global__ void init_kernel(int accLen) {
    int i = blockIdx.x * blockDim.x + threadIdx.x;
    if (i < accLen) g_accb[i] = 0.f;
    if (i < NN * HEADS) { g_max[i] = 0u; g_den[i] = 0.f; }
}

// ---------------- simple tiled fp32 GEMM: C[M,Ncol] = A[M,K] @ B[K,Ncol] ---
// 64x64 tile, TK=16, 256 threads, 4x4 register block per thread.
__global__ void gemm_kernel(const float* __restrict__ A, const float* __restrict__ B,
                            float* __restrict__ C, int M, int Ncol, int K) {
    __shared__ float As[16][65];
    __shared__ float Bs[16][64];
    int tid = threadIdx.x;
    int tx = tid & 15, ty = tid >> 4;
    int row0 = blockIdx.y * 64, col0 = blockIdx.x * 64;
    float acc[4][4] = {};
    for (int k0 = 0; k0 < K; k0 += 16) {
        for (int i = tid; i < 64 * 16; i += 256) {
            int m = i >> 4, kk = i & 15;
            int gr = row0 + m;
            As[kk][m] = (gr < M) ? A[(size_t)gr * K + k0 + kk] : 0.f;
        }
        for (int i = tid; i < 16 * 64; i += 256) {
            int nn = i & 63, kk = i >> 6;
            Bs[kk][nn] = B[(size_t)(k0 + kk) * Ncol + col0 + nn];
        }
        __syncthreads();
#pragma unroll
        for (int kk = 0; kk < 16; kk++) {
            float a[4], b[4];
#pragma unroll
            for (int i = 0; i < 4; i++) a[i] = As[kk][ty * 4 + i];
#pragma unroll
            for (int j = 0; j < 4; j++) b[j] = Bs[kk][tx * 4 + j];
#pragma unroll
            for (int i = 0; i < 4; i++)
#pragma unroll
                for (int j = 0; j < 4; j++) acc[i][j] += a[i] * b[j];
        }
        __syncthreads();
    }
#pragma unroll
    for (int i = 0; i < 4; i++) {
        int r = row0 + ty * 4 + i;
        if (r < M)
#pragma unroll
            for (int j = 0; j < 4; j++)
                C[(size_t)r * Ncol + col0 + tx * 4 + j] = acc[i][j];
    }
}

// ---------------- attention logits: al_s/al_d per (node, head) -------------
__global__ void al_kernel(const float* __restrict__ a_s, const float* __restrict__ a_d, int C) {
    int idx = blockIdx.x * blockDim.x + threadIdx.x;
    if (idx >= NN * HEADS) return;
    int n = idx >> 3, h = idx & 7;
    const float* f = g_feat + (size_t)n * HEADS * C + h * C;
    const float* w1 = a_s + h * C;
    const float* w2 = a_d + h * C;
    float s1 = 0.f, s2 = 0.f;
    for (int c = 0; c < C; c++) { float v = f[c]; s1 += v * w1[c]; s2 += v * w2[c]; }
    g_als[idx] = s1;
    g_ald[idx] = s2;
}

// ---------------- edge pass 1: segment max ---------------------------------
__global__ void edge_max_kernel() {
    int idx = blockIdx.x * blockDim.x + threadIdx.x;
    if (idx >= ET * HEADS) return;
    int e = idx >> 3, h = idx & 7;
    int s = g_src[e], d = g_dst[e];
    float ev = g_als[s * HEADS + h] + g_ald[d * HEADS + h];
    ev = ev > 0.f ? ev : 0.2f * ev;            // leaky_relu 0.2
    atomicMax(&g_max[d * HEADS + h], fenc(ev));
}

// ---------------- edge pass 2: softmax denominator -------------------------
__global__ void edge_den_kernel() {
    int idx = blockIdx.x * blockDim.x + threadIdx.x;
    if (idx >= ET * HEADS) return;
    int e = idx >> 3, h = idx & 7;
    int s = g_src[e], d = g_dst[e];
    float ev = g_als[s * HEADS + h] + g_ald[d * HEADS + h];
    ev = ev > 0.f ? ev : 0.2f * ev;
    float m = fdec(g_max[d * HEADS + h]);
    atomicAdd(&g_den[d * HEADS + h], expf(ev - m));
}

// ---------------- edge pass 3 (layers 0/1, C=32): scatter messages ---------
__global__ void edge_msg_small_kernel() {
    int gid = blockIdx.x * blockDim.x + threadIdx.x;
    int e = gid >> 5, lane = gid & 31;
    if (e >= ET) return;
    int s = g_src[e], d = g_dst[e];
    float alpha = 0.f;
    if (lane < HEADS) {
        float ev = g_als[s * HEADS + lane] + g_ald[d * HEADS + lane];
        ev = ev > 0.f ? ev : 0.2f * ev;
        float m = fdec(g_max[d * HEADS + lane]);
        alpha = expf(ev - m) / (g_den[d * HEADS + lane] + 1e-16f);
    }
    const float* f = g_feat + (size_t)s * 256;
    float* o = g_accb + (size_t)d * 256;
#pragma unroll
    for (int h = 0; h < HEADS; h++) {
        float a = __shfl_sync(0xffffffffu, alpha, h);
        int c = h * 32 + lane;
        atomicAdd(&o[c], a * f[c]);
    }
}

// ---------------- edge pass 3 (layer 2, C=128, mean over heads) ------------
__global__ void edge_msg_big_kernel() {
    int gid = blockIdx.x * blockDim.x + threadIdx.x;
    int e = gid >> 5, lane = gid & 31;
    if (e >= ET) return;
    int s = g_src[e], d = g_dst[e];
    float alpha = 0.f;
    if (lane < HEADS) {
        float ev = g_als[s * HEADS + lane] + g_ald[d * HEADS + lane];
        ev = ev > 0.f ? ev : 0.2f * ev;
        float m = fdec(g_max[d * HEADS + lane]);
        alpha = 0.125f * expf(ev - m) / (g_den[d * HEADS + lane] + 1e-16f);
    }
    const float* f = g_feat + (size_t)s * 1024;
    float* o = g_accb + (size_t)d * 128;
#pragma unroll
    for (int chunk = 0; chunk < 4; chunk++) {
        int c = chunk * 32 + lane;
        float msg = 0.f;
#pragma unroll
        for (int h = 0; h < HEADS; h++) {
            float a = __shfl_sync(0xffffffffu, alpha, h);
            msg += a * f[h * 128 + c];
        }
        atomicAdd(&o[c], msg);
    }
}

// ---------------- finalize layers 0/1: +bias, LN, +sig*res, ELU ------------
__global__ void finalize01_kernel(const float* __restrict__ bias,
                                  const float* __restrict__ lng, const float* __restrict__ lnb,
                                  const float* __restrict__ res, const float* __restrict__ rb,
                                  const float* __restrict__ rw, float* __restrict__ out) {
    int n = blockIdx.x, t = threadIdx.x;   // 256 threads
    float g = g_accb[(size_t)n * 256 + t] + bias[t];
    float s1 = g, s2 = g * g;
#pragma unroll
    for (int o = 16; o; o >>= 1) {
        s1 += __shfl_down_sync(0xffffffffu, s1, o);
        s2 += __shfl_down_sync(0xffffffffu, s2, o);
    }
    __shared__ float sh1[8], sh2[8];
    __shared__ float mu_s, rs_s;
    int w = t >> 5, l = t & 31;
    if (l == 0) { sh1[w] = s1; sh2[w] = s2; }
    __syncthreads();
    if (t == 0) {
        float a = 0.f, b = 0.f;
#pragma unroll
        for (int i = 0; i < 8; i++) { a += sh1[i]; b += sh2[i]; }
        float mu = a * (1.f / 256.f);
        float var = b * (1.f / 256.f) - mu * mu;
        mu_s = mu;
        rs_s = rsqrtf(var + 1e-5f);
    }
    __syncthreads();
    float y = (g - mu_s) * rs_s * lng[t] + lnb[t];
    float sig = 1.f / (1.f + expf(-rw[0]));
    float r = res[(size_t)n * 256 + t];
    if (rb) r += rb[t];
    float z = y + sig * r;
    out[(size_t)n * 256 + t] = z > 0.f ? z : expm1f(z);   // elu
}

// ---------------- finalize layer 2: +bias, LN, +sig*res (no elu) -----------
__global__ void finalize2_kernel(const float* __restrict__ bias,
                                 const float* __restrict__ lng, const float* __restrict__ lnb,
                                 const float* __restrict__ res, const float* __restrict__ rb,
                                 const float* __restrict__ rw, float* __restrict__ out) {
    int n = blockIdx.x, t = threadIdx.x;   // 128 threads
    float g = g_accb[(size_t)n * 128 + t] + bias[t];
    float s1 = g, s2 = g * g;
#pragma unroll
    for (int o = 16; o; o >>= 1) {
        s1 += __shfl_down_sync(0xffffffffu, s1, o);
        s2 += __shfl_down_sync(0xffffffffu, s2, o);
    }
    __shared__ float sh1[4], sh2[4];
    __shared__ float mu_s, rs_s;
    int w = t >> 5, l = t & 31;
    if (l == 0) { sh1[w] = s1; sh2[w] = s2; }
    __syncthreads();
    if (t == 0) {
        float a = 0.f, b = 0.f;
#pragma unroll
        for (int i = 0; i < 4; i++) { a += sh1[i]; b += sh2[i]; }
        float mu = a * (1.f / 128.f);
        float var = b * (1.f / 128.f) - mu * mu;
        mu_s = mu;
        rs_s = rsqrtf(var + 1e-5f);
    }
    __syncthreads();
    float y = (g - mu_s) * rs_s * lng[t] + lnb[t];
    float sig = 1.f / (1.f + expf(-rw[0]));
    float r = res[(size_t)n * 128 + t] + rb[t];
    out[(size_t)n * 128 + t] = y + sig * r;
}

// ---------------------------------------------------------------------------
extern "C" void kernel_launch(void* const* d_in, const int* in_sizes, int n_in,
                              void* d_out, int out_size) {
    const float* x   = (const float*)d_in[0];
    const void*  ei  = d_in[1];                   // int32 or int64, detected on device
    const float* W0  = (const float*)d_in[2];
    const float* b0  = (const float*)d_in[3];
    const float* as0 = (const float*)d_in[4];
    const float* ad0 = (const float*)d_in[5];
    const float* lng0= (const float*)d_in[6];
    const float* lnb0= (const float*)d_in[7];
    const float* rW0 = (const float*)d_in[8];
    const float* rb0 = (const float*)d_in[9];
    const float* rw0 = (const float*)d_in[10];
    const float* W1  = (const float*)d_in[11];
    const float* b1  = (const float*)d_in[12];
    const float* as1 = (const float*)d_in[13];
    const float* ad1 = (const float*)d_in[14];
    const float* lng1= (const float*)d_in[15];
    const float* lnb1= (const float*)d_in[16];
    const float* rw1 = (const float*)d_in[17];
    const float* W2  = (const float*)d_in[18];
    const float* b2  = (const float*)d_in[19];
    const float* as2 = (const float*)d_in[20];
    const float* ad2 = (const float*)d_in[21];
    const float* lng2= (const float*)d_in[22];
    const float* lnb2= (const float*)d_in[23];
    const float* rW2 = (const float*)d_in[24];
    const float* rb2 = (const float*)d_in[25];
    const float* rw2 = (const float*)d_in[26];

    float *feat, *act0, *act1, *res;
    cudaGetSymbolAddress((void**)&feat, g_feat);
    cudaGetSymbolAddress((void**)&act0, g_act0);
    cudaGetSymbolAddress((void**)&act1, g_act1);
    cudaGetSymbolAddress((void**)&res,  g_resb);

    const int TB = 256;
    detect_kernel<<<1, 256>>>((const int*)ei);
    build_edges_kernel<<<(ET + TB - 1) / TB, TB>>>(ei);

    dim3 gemmGridM((NN + 63) / 64);
    int alBlocks   = (NN * HEADS + TB - 1) / TB;
    int edgeBlocks = (ET * HEADS + TB - 1) / TB;
    int msgBlocks  = (ET * 32 + TB - 1) / TB;

    // ---------------- layer 0 ----------------
    gemm_kernel<<<dim3(4, gemmGridM.x), TB>>>(x, W0, feat, NN, 256, 64);
    gemm_kernel<<<dim3(4, gemmGridM.x), TB>>>(x, rW0, res, NN, 256, 64);
    al_kernel<<<alBlocks, TB>>>(as0, ad0, 32);
    init_kernel<<<(NN * 256 + TB - 1) / TB, TB>>>(NN * 256);
    edge_max_kernel<<<edgeBlocks, TB>>>();
    edge_den_kernel<<<edgeBlocks, TB>>>();
    edge_msg_small_kernel<<<msgBlocks, TB>>>();
    finalize01_kernel<<<NN, 256>>>(b0, lng0, lnb0, res, rb0, rw0, act0);

    // ---------------- layer 1 ----------------
    gemm_kernel<<<dim3(4, gemmGridM.x), TB>>>(act0, W1, feat, NN, 256, 256);
    al_kernel<<<alBlocks, TB>>>(as1, ad1, 32);
    init_kernel<<<(NN * 256 + TB - 1) / TB, TB>>>(NN * 256);
    edge_max_kernel<<<edgeBlocks, TB>>>();
    edge_den_kernel<<<edgeBlocks, TB>>>();
    edge_msg_small_kernel<<<msgBlocks, TB>>>();
    finalize01_kernel<<<NN, 256>>>(b1, lng1, lnb1, act0, nullptr, rw1, act1);

    // ---------------- layer 2 ----------------
    gemm_kernel<<<dim3(16, gemmGridM.x), TB>>>(act1, W2, feat, NN, 1024, 256);
    gemm_kernel<<<dim3(2, gemmGridM.x), TB>>>(act1, rW2, res, NN, 128, 256);
    al_kernel<<<alBlocks, TB>>>(as2, ad2, 128);
    init_kernel<<<(NN * 128 + TB - 1) / TB, TB>>>(NN * 128);
    edge_max_kernel<<<edgeBlocks, TB>>>();
    edge_den_kernel<<<edgeBlocks, TB>>>();
    edge_msg_big_kernel<<<msgBlocks, TB>>>();
    finalize2_kernel<<<NN, 128>>>(b2, lng2, lnb2, res, rb2, rw2, (float*)d_out);
}

// round 5
// speedup vs baseline: 1.3058x; 1.3058x over previous
#include <cuda_runtime.h>
#include <cuda_bf16.h>
#include <mma.h>
using namespace nvcuda;

// Problem constants (fixed by the reference)
#define NN 20000
#define EE 320000
#define ET (NN + EE)          // edges incl. self loops = 340000
#define HEADS 8
#define MP 20096              // NN padded to multiple of 128 for tensor GEMM

// ---------------- scratch (device globals: no allocation allowed) ----------
__device__ float g_feat[(size_t)MP * 1024];   // transformed features (max layer2: MP x 1024)
__device__ float g_accb[(size_t)NN * 256];    // aggregation accumulator
__device__ float g_act0[(size_t)NN * 256];    // activation after layer 0
__device__ float g_act1[(size_t)NN * 256];    // activation after layer 1
__device__ float g_resb[(size_t)MP * 256];    // residual projection
__device__ float g_als[NN * HEADS];
__device__ float g_ald[NN * HEADS];
__device__ float g_den[NN * HEADS];
__device__ unsigned g_max[NN * HEADS];
__device__ int g_src[ET];
__device__ int g_dst[ET];
__device__ int g_is64;

// bf16 split buffers for tensor-core GEMM
__device__ __nv_bfloat16 g_Ah[(size_t)MP * 256];
__device__ __nv_bfloat16 g_Al[(size_t)MP * 256];
__device__ __nv_bfloat16 g_Bh[256 * 1024];
__device__ __nv_bfloat16 g_Bl[256 * 1024];

// Ordered-uint encoding of float for atomicMax over signed floats
__device__ __forceinline__ unsigned fenc(float f) {
    unsigned u = __float_as_uint(f);
    return (u & 0x80000000u) ? ~u : (u | 0x80000000u);
}
__device__ __forceinline__ float fdec(unsigned u) {
    return (u & 0x80000000u) ? __uint_as_float(u ^ 0x80000000u)
                             : __uint_as_float(~u);
}

// ---------------- dtype detection: int64 vs int32 edge_index ---------------
__global__ void detect_kernel(const int* __restrict__ raw) {
    __shared__ int any;
    if (threadIdx.x == 0) any = 0;
    __syncthreads();
    for (int i = threadIdx.x; i < 2048; i += blockDim.x)
        if (raw[2 * i + 1] != 0) any = 1;
    __syncthreads();
    if (threadIdx.x == 0) g_is64 = (any == 0);
}

// ---------------- edge list build (append self loops) ----------------------
__global__ void build_edges_kernel(const void* __restrict__ eiraw) {
    int i = blockIdx.x * blockDim.x + threadIdx.x;
    if (i >= ET) return;
    int s, d;
    if (i < EE) {
        if (g_is64) {
            const long long* e = (const long long*)eiraw;
            s = (int)e[i];
            d = (int)e[EE + i];
        } else {
            const int* e = (const int*)eiraw;
            s = e[i];
            d = e[EE + i];
        }
        s = min(max(s, 0), NN - 1);
        d = min(max(d, 0), NN - 1);
    } else {
        s = d = i - EE;   // self loop
    }
    g_src[i] = s;
    g_dst[i] = d;
}

// ---------------- per-layer init: zero acc, reset max/denom ----------------
__global__ void init_kernel(int accLen) {
    int i = blockIdx.x * blockDim.x + threadIdx.x;
    if (i < accLen) g_accb[i] = 0.f;
    if (i < NN * HEADS) { g_max[i] = 0u; g_den[i] = 0.f; }
}

// ---------------- fp32 -> bf16 hi/lo split ----------------------------------
// Elements beyond realElems are zero-filled (row padding to MP rows).
__global__ void split_kernel(const float* __restrict__ X,
                             __nv_bfloat16* __restrict__ H,
                             __nv_bfloat16* __restrict__ L,
                             int realElems, int totElems) {
    int i = blockIdx.x * blockDim.x + threadIdx.x;
    if (i >= totElems) return;
    float v = (i < realElems) ? X[i] : 0.f;
    __nv_bfloat16 h = __float2bfloat16(v);
    H[i] = h;
    L[i] = __float2bfloat16(v - __bfloat162float(h));
}

// ---------------- tensor-core GEMM: C[MP,N] = A[MP,K] @ B[K,N] -------------
// Split-bf16 3-product: C = Ah*Bh + Al*Bh + Ah*Bl, fp32 accumulate.
// Block tile 128x128, BK=32, 8 warps, each warp 64x32 (4x2 wmma 16x16 frags).
// M is padded to a multiple of 128 (MP); A buffers are zero-padded, C buffers
// oversized, so no bounds checks anywhere.
struct __align__(256) SmemA { __nv_bfloat16 d[128][40]; };
struct __align__(256) SmemB { __nv_bfloat16 d[32][136]; };

__global__ void __launch_bounds__(256) gemm_tc_kernel(
    const __nv_bfloat16* __restrict__ Ah, const __nv_bfloat16* __restrict__ Al,
    const __nv_bfloat16* __restrict__ Bh, const __nv_bfloat16* __restrict__ Bl,
    float* __restrict__ C, int N, int K)
{
    __shared__ SmemA sAh, sAl;
    __shared__ SmemB sBh, sBl;
    int tid = threadIdx.x;
    int warp = tid >> 5;
    int wm = warp & 1, wn = warp >> 1;           // 2 x 4 warp grid
    int row0 = blockIdx.y * 128, col0 = blockIdx.x * 128;

    wmma::fragment<wmma::accumulator, 16, 16, 16, float> acc[4][2];
#pragma unroll
    for (int i = 0; i < 4; i++)
#pragma unroll
        for (int j = 0; j < 2; j++) wmma::fill_fragment(acc[i][j], 0.f);

    for (int k0 = 0; k0 < K; k0 += 32) {
        // A tiles: 128 rows x 32 k (8-elem vector loads)
#pragma unroll
        for (int v = tid; v < 512; v += 256) {
            int r = v >> 2, kk = (v & 3) * 8;
            size_t g = (size_t)(row0 + r) * K + k0 + kk;
            *(uint4*)&sAh.d[r][kk] = *(const uint4*)&Ah[g];
            *(uint4*)&sAl.d[r][kk] = *(const uint4*)&Al[g];
        }
        // B tiles: 32 k x 128 cols
#pragma unroll
        for (int v = tid; v < 512; v += 256) {
            int r = v >> 4, cc = (v & 15) * 8;
            size_t g = (size_t)(k0 + r) * N + col0 + cc;
            *(uint4*)&sBh.d[r][cc] = *(const uint4*)&Bh[g];
            *(uint4*)&sBl.d[r][cc] = *(const uint4*)&Bl[g];
        }
        __syncthreads();
#pragma unroll
        for (int ks = 0; ks < 32; ks += 16) {
            wmma::fragment<wmma::matrix_a, 16, 16, 16, __nv_bfloat16, wmma::row_major> fah[4], fal[4];
            wmma::fragment<wmma::matrix_b, 16, 16, 16, __nv_bfloat16, wmma::row_major> fbh[2], fbl[2];
#pragma unroll
            for (int i = 0; i < 4; i++) {
                wmma::load_matrix_sync(fah[i], &sAh.d[wm * 64 + i * 16][ks], 40);
                wmma::load_matrix_sync(fal[i], &sAl.d[wm * 64 + i * 16][ks], 40);
            }
#pragma unroll
            for (int j = 0; j < 2; j++) {
                wmma::load_matrix_sync(fbh[j], &sBh.d[ks][wn * 32 + j * 16], 136);
                wmma::load_matrix_sync(fbl[j], &sBl.d[ks][wn * 32 + j * 16], 136);
            }
#pragma unroll
            for (int i = 0; i < 4; i++)
#pragma unroll
                for (int j = 0; j < 2; j++) {
                    wmma::mma_sync(acc[i][j], fah[i], fbh[j], acc[i][j]);
                    wmma::mma_sync(acc[i][j], fal[i], fbh[j], acc[i][j]);
                    wmma::mma_sync(acc[i][j], fah[i], fbl[j], acc[i][j]);
                }
        }
        __syncthreads();
    }
#pragma unroll
    for (int i = 0; i < 4; i++)
#pragma unroll
        for (int j = 0; j < 2; j++)
            wmma::store_matrix_sync(&C[(size_t)(row0 + wm * 64 + i * 16) * N +
                                       col0 + wn * 32 + j * 16],
                                    acc[i][j], N, wmma::mem_row_major);
}

// ---------------- attention logits: al_s/al_d per (node, head) -------------
__global__ void al_kernel(const float* __restrict__ a_s, const float* __restrict__ a_d, int C) {
    int idx = blockIdx.x * blockDim.x + threadIdx.x;
    if (idx >= NN * HEADS) return;
    int n = idx >> 3, h = idx & 7;
    const float* f = g_feat + (size_t)n * HEADS * C + h * C;
    const float* w1 = a_s + h * C;
    const float* w2 = a_d + h * C;
    float s1 = 0.f, s2 = 0.f;
    for (int c = 0; c < C; c++) { float v = f[c]; s1 += v * w1[c]; s2 += v * w2[c]; }
    g_als[idx] = s1;
    g_ald[idx] = s2;
}

// ---------------- edge pass 1: segment max ---------------------------------
__global__ void edge_max_kernel() {
    int idx = blockIdx.x * blockDim.x + threadIdx.x;
    if (idx >= ET * HEADS) return;
    int e = idx >> 3, h = idx & 7;
    int s = g_src[e], d = g_dst[e];
    float ev = g_als[s * HEADS + h] + g_ald[d * HEADS + h];
    ev = ev > 0.f ? ev : 0.2f * ev;            // leaky_relu 0.2
    atomicMax(&g_max[d * HEADS + h], fenc(ev));
}

// ---------------- edge pass 2: softmax denominator -------------------------
__global__ void edge_den_kernel() {
    int idx = blockIdx.x * blockDim.x + threadIdx.x;
    if (idx >= ET * HEADS) return;
    int e = idx >> 3, h = idx & 7;
    int s = g_src[e], d = g_dst[e];
    float ev = g_als[s * HEADS + h] + g_ald[d * HEADS + h];
    ev = ev > 0.f ? ev : 0.2f * ev;
    float m = fdec(g_max[d * HEADS + h]);
    atomicAdd(&g_den[d * HEADS + h], expf(ev - m));
}

// ---------------- edge pass 3 (layers 0/1, C=32): scatter messages ---------
__global__ void edge_msg_small_kernel() {
    int gid = blockIdx.x * blockDim.x + threadIdx.x;
    int e = gid >> 5, lane = gid & 31;
    if (e >= ET) return;
    int s = g_src[e], d = g_dst[e];
    float alpha = 0.f;
    if (lane < HEADS) {
        float ev = g_als[s * HEADS + lane] + g_ald[d * HEADS + lane];
        ev = ev > 0.f ? ev : 0.2f * ev;
        float m = fdec(g_max[d * HEADS + lane]);
        alpha = expf(ev - m) / (g_den[d * HEADS + lane] + 1e-16f);
    }
    const float* f = g_feat + (size_t)s * 256;
    float* o = g_accb + (size_t)d * 256;
#pragma unroll
    for (int h = 0; h < HEADS; h++) {
        float a = __shfl_sync(0xffffffffu, alpha, h);
        int c = h * 32 + lane;
        atomicAdd(&o[c], a * f[c]);
    }
}

// ---------------- edge pass 3 (layer 2, C=128, mean over heads) ------------
__global__ void edge_msg_big_kernel() {
    int gid = blockIdx.x * blockDim.x + threadIdx.x;
    int e = gid >> 5, lane = gid & 31;
    if (e >= ET) return;
    int s = g_src[e], d = g_dst[e];
    float alpha = 0.f;
    if (lane < HEADS) {
        float ev = g_als[s * HEADS + lane] + g_ald[d * HEADS + lane];
        ev = ev > 0.f ? ev : 0.2f * ev;
        float m = fdec(g_max[d * HEADS + lane]);
        alpha = 0.125f * expf(ev - m) / (g_den[d * HEADS + lane] + 1e-16f);
    }
    const float* f = g_feat + (size_t)s * 1024;
    float* o = g_accb + (size_t)d * 128;
#pragma unroll
    for (int chunk = 0; chunk < 4; chunk++) {
        int c = chunk * 32 + lane;
        float msg = 0.f;
#pragma unroll
        for (int h = 0; h < HEADS; h++) {
            float a = __shfl_sync(0xffffffffu, alpha, h);
            msg += a * f[h * 128 + c];
        }
        atomicAdd(&o[c], msg);
    }
}

// ---------------- finalize layers 0/1: +bias, LN, +sig*res, ELU ------------
__global__ void finalize01_kernel(const float* __restrict__ bias,
                                  const float* __restrict__ lng, const float* __restrict__ lnb,
                                  const float* __restrict__ res, const float* __restrict__ rb,
                                  const float* __restrict__ rw, float* __restrict__ out) {
    int n = blockIdx.x, t = threadIdx.x;   // 256 threads
    float g = g_accb[(size_t)n * 256 + t] + bias[t];
    float s1 = g, s2 = g * g;
#pragma unroll
    for (int o = 16; o; o >>= 1) {
        s1 += __shfl_down_sync(0xffffffffu, s1, o);
        s2 += __shfl_down_sync(0xffffffffu, s2, o);
    }
    __shared__ float sh1[8], sh2[8];
    __shared__ float mu_s, rs_s;
    int w = t >> 5, l = t & 31;
    if (l == 0) { sh1[w] = s1; sh2[w] = s2; }
    __syncthreads();
    if (t == 0) {
        float a = 0.f, b = 0.f;
#pragma unroll
        for (int i = 0; i < 8; i++) { a += sh1[i]; b += sh2[i]; }
        float mu = a * (1.f / 256.f);
        float var = b * (1.f / 256.f) - mu * mu;
        mu_s = mu;
        rs_s = rsqrtf(var + 1e-5f);
    }
    __syncthreads();
    float y = (g - mu_s) * rs_s * lng[t] + lnb[t];
    float sig = 1.f / (1.f + expf(-rw[0]));
    float r = res[(size_t)n * 256 + t];
    if (rb) r += rb[t];
    float z = y + sig * r;
    out[(size_t)n * 256 + t] = z > 0.f ? z : expm1f(z);   // elu
}

// ---------------- finalize layer 2: +bias, LN, +sig*res (no elu) -----------
__global__ void finalize2_kernel(const float* __restrict__ bias,
                                 const float* __restrict__ lng, const float* __restrict__ lnb,
                                 const float* __restrict__ res, const float* __restrict__ rb,
                                 const float* __restrict__ rw, float* __restrict__ out) {
    int n = blockIdx.x, t = threadIdx.x;   // 128 threads
    float g = g_accb[(size_t)n * 128 + t] + bias[t];
    float s1 = g, s2 = g * g;
#pragma unroll
    for (int o = 16; o; o >>= 1) {
        s1 += __shfl_down_sync(0xffffffffu, s1, o);
        s2 += __shfl_down_sync(0xffffffffu, s2, o);
    }
    __shared__ float sh1[4], sh2[4];
    __shared__ float mu_s, rs_s;
    int w = t >> 5, l = t & 31;
    if (l == 0) { sh1[w] = s1; sh2[w] = s2; }
    __syncthreads();
    if (t == 0) {
        float a = 0.f, b = 0.f;
#pragma unroll
        for (int i = 0; i < 4; i++) { a += sh1[i]; b += sh2[i]; }
        float mu = a * (1.f / 128.f);
        float var = b * (1.f / 128.f) - mu * mu;
        mu_s = mu;
        rs_s = rsqrtf(var + 1e-5f);
    }
    __syncthreads();
    float y = (g - mu_s) * rs_s * lng[t] + lnb[t];
    float sig = 1.f / (1.f + expf(-rw[0]));
    float r = res[(size_t)n * 128 + t] + rb[t];
    out[(size_t)n * 128 + t] = y + sig * r;
}

// ---------------------------------------------------------------------------
extern "C" void kernel_launch(void* const* d_in, const int* in_sizes, int n_in,
                              void* d_out, int out_size) {
    const float* x   = (const float*)d_in[0];
    const void*  ei  = d_in[1];                   // int32 or int64, detected on device
    const float* W0  = (const float*)d_in[2];
    const float* b0  = (const float*)d_in[3];
    const float* as0 = (const float*)d_in[4];
    const float* ad0 = (const float*)d_in[5];
    const float* lng0= (const float*)d_in[6];
    const float* lnb0= (const float*)d_in[7];
    const float* rW0 = (const float*)d_in[8];
    const float* rb0 = (const float*)d_in[9];
    const float* rw0 = (const float*)d_in[10];
    const float* W1  = (const float*)d_in[11];
    const float* b1  = (const float*)d_in[12];
    const float* as1 = (const float*)d_in[13];
    const float* ad1 = (const float*)d_in[14];
    const float* lng1= (const float*)d_in[15];
    const float* lnb1= (const float*)d_in[16];
    const float* rw1 = (const float*)d_in[17];
    const float* W2  = (const float*)d_in[18];
    const float* b2  = (const float*)d_in[19];
    const float* as2 = (const float*)d_in[20];
    const float* ad2 = (const float*)d_in[21];
    const float* lng2= (const float*)d_in[22];
    const float* lnb2= (const float*)d_in[23];
    const float* rW2 = (const float*)d_in[24];
    const float* rb2 = (const float*)d_in[25];
    const float* rw2 = (const float*)d_in[26];

    float *feat, *act0, *act1, *res;
    __nv_bfloat16 *Ah, *Al, *Bh, *Bl;
    cudaGetSymbolAddress((void**)&feat, g_feat);
    cudaGetSymbolAddress((void**)&act0, g_act0);
    cudaGetSymbolAddress((void**)&act1, g_act1);
    cudaGetSymbolAddress((void**)&res,  g_resb);
    cudaGetSymbolAddress((void**)&Ah, g_Ah);
    cudaGetSymbolAddress((void**)&Al, g_Al);
    cudaGetSymbolAddress((void**)&Bh, g_Bh);
    cudaGetSymbolAddress((void**)&Bl, g_Bl);

    const int TB = 256;
    detect_kernel<<<1, 256>>>((const int*)ei);
    build_edges_kernel<<<(ET + TB - 1) / TB, TB>>>(ei);

    int alBlocks   = (NN * HEADS + TB - 1) / TB;
    int edgeBlocks = (ET * HEADS + TB - 1) / TB;
    int msgBlocks  = (ET * 32 + TB - 1) / TB;
    const int MROWS = MP / 128;   // 157

    auto splitN = [&](const float* src, __nv_bfloat16* h, __nv_bfloat16* l,
                      int realE, int totE) {
        split_kernel<<<(totE + TB - 1) / TB, TB>>>(src, h, l, realE, totE);
    };

    // ---------------- layer 0 ----------------
    splitN(x, Ah, Al, NN * 64, MP * 64);
    splitN(W0, Bh, Bl, 64 * 256, 64 * 256);
    gemm_tc_kernel<<<dim3(2, MROWS), 256>>>(Ah, Al, Bh, Bl, feat, 256, 64);
    splitN(rW0, Bh, Bl, 64 * 256, 64 * 256);
    gemm_tc_kernel<<<dim3(2, MROWS), 256>>>(Ah, Al, Bh, Bl, res, 256, 64);
    al_kernel<<<alBlocks, TB>>>(as0, ad0, 32);
    init_kernel<<<(NN * 256 + TB - 1) / TB, TB>>>(NN * 256);
    edge_max_kernel<<<edgeBlocks, TB>>>();
    edge_den_kernel<<<edgeBlocks, TB>>>();
    edge_msg_small_kernel<<<msgBlocks, TB>>>();
    finalize01_kernel<<<NN, 256>>>(b0, lng0, lnb0, res, rb0, rw0, act0);

    // ---------------- layer 1 ----------------
    splitN(act0, Ah, Al, NN * 256, MP * 256);
    splitN(W1, Bh, Bl, 256 * 256, 256 * 256);
    gemm_tc_kernel<<<dim3(2, MROWS), 256>>>(Ah, Al, Bh, Bl, feat, 256, 256);
    al_kernel<<<alBlocks, TB>>>(as1, ad1, 32);
    init_kernel<<<(NN * 256 + TB - 1) / TB, TB>>>(NN * 256);
    edge_max_kernel<<<edgeBlocks, TB>>>();
    edge_den_kernel<<<edgeBlocks, TB>>>();
    edge_msg_small_kernel<<<msgBlocks, TB>>>();
    finalize01_kernel<<<NN, 256>>>(b1, lng1, lnb1, act0, nullptr, rw1, act1);

    // ---------------- layer 2 ----------------
    splitN(act1, Ah, Al, NN * 256, MP * 256);
    splitN(W2, Bh, Bl, 256 * 1024, 256 * 1024);
    gemm_tc_kernel<<<dim3(8, MROWS), 256>>>(Ah, Al, Bh, Bl, feat, 1024, 256);
    splitN(rW2, Bh, Bl, 256 * 128, 256 * 128);
    gemm_tc_kernel<<<dim3(1, MROWS), 256>>>(Ah, Al, Bh, Bl, res, 128, 256);
    al_kernel<<<alBlocks, TB>>>(as2, ad2, 128);
    init_kernel<<<(NN * 128 + TB - 1) / TB, TB>>>(NN * 128);
    edge_max_kernel<<<edgeBlocks, TB>>>();
    edge_den_kernel<<<edgeBlocks, TB>>>();
    edge_msg_big_kernel<<<msgBlocks, TB>>>();
    finalize2_kernel<<<NN, 128>>>(b2, lng2, lnb2, res, rb2, rw2, (float*)d_out);
}

// round 6
// speedup vs baseline: 1.4949x; 1.1449x over previous
#include <cuda_runtime.h>
#include <cuda_bf16.h>
#include <mma.h>
using namespace nvcuda;

// Problem constants (fixed by the reference)
#define NN 20000
#define EE 320000
#define ET (NN + EE)          // edges incl. self loops = 340000
#define HEADS 8
#define MP 20096              // NN padded to multiple of 128 for tensor GEMM

// ---------------- scratch (device globals: no allocation allowed) ----------
__device__ float g_feat[(size_t)MP * 1024];   // transformed features (max layer2: MP x 1024)
__device__ float g_accb[(size_t)NN * 256];    // aggregation output
__device__ float g_act0[(size_t)NN * 256];    // activation after layer 0
__device__ float g_act1[(size_t)NN * 256];    // activation after layer 1
__device__ float g_resb[(size_t)MP * 256];    // residual projection
__device__ float g_als[NN * HEADS];
__device__ float g_ald[NN * HEADS];
__device__ int g_src[ET];
__device__ int g_dst[ET];
__device__ int g_is64;
// CSR (dst-sorted adjacency)
__device__ int g_deg[NN];
__device__ int g_off[NN + 1];
__device__ int g_cur[NN];
__device__ int g_csr_src[ET];

// bf16 split buffers for tensor-core GEMM
__device__ __nv_bfloat16 g_Ah[(size_t)MP * 256];
__device__ __nv_bfloat16 g_Al[(size_t)MP * 256];
__device__ __nv_bfloat16 g_Bh[256 * 1024];
__device__ __nv_bfloat16 g_Bl[256 * 1024];

// ---------------- dtype detection: int64 vs int32 edge_index ---------------
__global__ void detect_kernel(const int* __restrict__ raw) {
    __shared__ int any;
    if (threadIdx.x == 0) any = 0;
    __syncthreads();
    for (int i = threadIdx.x; i < 2048; i += blockDim.x)
        if (raw[2 * i + 1] != 0) any = 1;
    __syncthreads();
    if (threadIdx.x == 0) g_is64 = (any == 0);
}

// ---------------- edge list build (append self loops), zero degrees --------
__global__ void build_edges_kernel(const void* __restrict__ eiraw) {
    int i = blockIdx.x * blockDim.x + threadIdx.x;
    if (i < NN) g_deg[i] = 0;
    if (i >= ET) return;
    int s, d;
    if (i < EE) {
        if (g_is64) {
            const long long* e = (const long long*)eiraw;
            s = (int)e[i];
            d = (int)e[EE + i];
        } else {
            const int* e = (const int*)eiraw;
            s = e[i];
            d = e[EE + i];
        }
        s = min(max(s, 0), NN - 1);
        d = min(max(d, 0), NN - 1);
    } else {
        s = d = i - EE;   // self loop
    }
    g_src[i] = s;
    g_dst[i] = d;
}

// ---------------- CSR build: histogram, scan, scatter ----------------------
__global__ void hist_kernel() {
    int i = blockIdx.x * blockDim.x + threadIdx.x;
    if (i < ET) atomicAdd(&g_deg[g_dst[i]], 1);
}

// single-block exclusive scan of g_deg[NN] -> g_off, g_cur
__global__ void scan_kernel() {
    __shared__ int ssum[1024];
    int t = threadIdx.x;
    const int PER = (NN + 1023) / 1024;   // 20
    int base = t * PER;
    int s = 0;
    for (int i = 0; i < PER; i++) {
        int idx = base + i;
        if (idx < NN) s += g_deg[idx];
    }
    ssum[t] = s;
    __syncthreads();
    int mine = s;
    for (int off = 1; off < 1024; off <<= 1) {
        int u = (t >= off) ? ssum[t - off] : 0;
        __syncthreads();
        ssum[t] += u;
        __syncthreads();
    }
    int run = ssum[t] - mine;             // exclusive offset for this thread's chunk
    for (int i = 0; i < PER; i++) {
        int idx = base + i;
        if (idx < NN) {
            g_off[idx] = run;
            g_cur[idx] = run;
            run += g_deg[idx];
        }
    }
    if (t == 1023) g_off[NN] = ET;
}

__global__ void scatter_kernel() {
    int i = blockIdx.x * blockDim.x + threadIdx.x;
    if (i >= ET) return;
    int d = g_dst[i];
    int pos = atomicAdd(&g_cur[d], 1);
    g_csr_src[pos] = g_src[i];
}

// ---------------- fp32 -> bf16 hi/lo split (vectorized x4) ------------------
__global__ void split_kernel(const float* __restrict__ X,
                             __nv_bfloat16* __restrict__ H,
                             __nv_bfloat16* __restrict__ L,
                             int realElems, int totElems) {
    int i = (blockIdx.x * blockDim.x + threadIdx.x) * 4;
    if (i >= totElems) return;
    float4 v = (i < realElems) ? *(const float4*)&X[i] : make_float4(0.f, 0.f, 0.f, 0.f);
    __nv_bfloat162 h01 = {__float2bfloat16(v.x), __float2bfloat16(v.y)};
    __nv_bfloat162 h23 = {__float2bfloat16(v.z), __float2bfloat16(v.w)};
    __nv_bfloat162 l01 = {__float2bfloat16(v.x - __bfloat162float(h01.x)),
                          __float2bfloat16(v.y - __bfloat162float(h01.y))};
    __nv_bfloat162 l23 = {__float2bfloat16(v.z - __bfloat162float(h23.x)),
                          __float2bfloat16(v.w - __bfloat162float(h23.y))};
    *(__nv_bfloat162*)&H[i] = h01;
    *(__nv_bfloat162*)&H[i + 2] = h23;
    *(__nv_bfloat162*)&L[i] = l01;
    *(__nv_bfloat162*)&L[i + 2] = l23;
}

// ---------------- tensor-core GEMM: C[MP,N] = A[MP,K] @ B[K,N] -------------
struct __align__(256) SmemA { __nv_bfloat16 d[128][40]; };
struct __align__(256) SmemB { __nv_bfloat16 d[32][136]; };

__global__ void __launch_bounds__(256) gemm_tc_kernel(
    const __nv_bfloat16* __restrict__ Ah, const __nv_bfloat16* __restrict__ Al,
    const __nv_bfloat16* __restrict__ Bh, const __nv_bfloat16* __restrict__ Bl,
    float* __restrict__ C, int N, int K)
{
    __shared__ SmemA sAh, sAl;
    __shared__ SmemB sBh, sBl;
    int tid = threadIdx.x;
    int warp = tid >> 5;
    int wm = warp & 1, wn = warp >> 1;           // 2 x 4 warp grid
    int row0 = blockIdx.y * 128, col0 = blockIdx.x * 128;

    wmma::fragment<wmma::accumulator, 16, 16, 16, float> acc[4][2];
#pragma unroll
    for (int i = 0; i < 4; i++)
#pragma unroll
        for (int j = 0; j < 2; j++) wmma::fill_fragment(acc[i][j], 0.f);

    for (int k0 = 0; k0 < K; k0 += 32) {
#pragma unroll
        for (int v = tid; v < 512; v += 256) {
            int r = v >> 2, kk = (v & 3) * 8;
            size_t g = (size_t)(row0 + r) * K + k0 + kk;
            *(uint4*)&sAh.d[r][kk] = *(const uint4*)&Ah[g];
            *(uint4*)&sAl.d[r][kk] = *(const uint4*)&Al[g];
        }
#pragma unroll
        for (int v = tid; v < 512; v += 256) {
            int r = v >> 4, cc = (v & 15) * 8;
            size_t g = (size_t)(k0 + r) * N + col0 + cc;
            *(uint4*)&sBh.d[r][cc] = *(const uint4*)&Bh[g];
            *(uint4*)&sBl.d[r][cc] = *(const uint4*)&Bl[g];
        }
        __syncthreads();
#pragma unroll
        for (int ks = 0; ks < 32; ks += 16) {
            wmma::fragment<wmma::matrix_a, 16, 16, 16, __nv_bfloat16, wmma::row_major> fah[4], fal[4];
            wmma::fragment<wmma::matrix_b, 16, 16, 16, __nv_bfloat16, wmma::row_major> fbh[2], fbl[2];
#pragma unroll
            for (int i = 0; i < 4; i++) {
                wmma::load_matrix_sync(fah[i], &sAh.d[wm * 64 + i * 16][ks], 40);
                wmma::load_matrix_sync(fal[i], &sAl.d[wm * 64 + i * 16][ks], 40);
            }
#pragma unroll
            for (int j = 0; j < 2; j++) {
                wmma::load_matrix_sync(fbh[j], &sBh.d[ks][wn * 32 + j * 16], 136);
                wmma::load_matrix_sync(fbl[j], &sBl.d[ks][wn * 32 + j * 16], 136);
            }
#pragma unroll
            for (int i = 0; i < 4; i++)
#pragma unroll
                for (int j = 0; j < 2; j++) {
                    wmma::mma_sync(acc[i][j], fah[i], fbh[j], acc[i][j]);
                    wmma::mma_sync(acc[i][j], fal[i], fbh[j], acc[i][j]);
                    wmma::mma_sync(acc[i][j], fah[i], fbl[j], acc[i][j]);
                }
        }
        __syncthreads();
    }
#pragma unroll
    for (int i = 0; i < 4; i++)
#pragma unroll
        for (int j = 0; j < 2; j++)
            wmma::store_matrix_sync(&C[(size_t)(row0 + wm * 64 + i * 16) * N +
                                       col0 + wn * 32 + j * 16],
                                    acc[i][j], N, wmma::mem_row_major);
}

// ---------------- attention logits: al_s/al_d per (node, head) -------------
__global__ void al_kernel(const float* __restrict__ a_s, const float* __restrict__ a_d, int C) {
    int idx = blockIdx.x * blockDim.x + threadIdx.x;
    if (idx >= NN * HEADS) return;
    int n = idx >> 3, h = idx & 7;
    const float* f = g_feat + (size_t)n * HEADS * C + h * C;
    const float* w1 = a_s + h * C;
    const float* w2 = a_d + h * C;
    float s1 = 0.f, s2 = 0.f;
    for (int c = 0; c < C; c++) { float v = f[c]; s1 += v * w1[c]; s2 += v * w2[c]; }
    g_als[idx] = s1;
    g_ald[idx] = s2;
}

// ---------------- fused aggregation (layers 0/1, C=32), warp per dst -------
// Pass A: per-head max + denom over neighbor list (lane-strided edges,
// shfl_xor 8/16 segmented reduction). Pass B: register accumulation of
// alpha-weighted gathered rows. No atomics.
__global__ void __launch_bounds__(256) agg_small_kernel(const float* __restrict__ feat,
                                                        float* __restrict__ out) {
    int wid = (blockIdx.x * blockDim.x + threadIdx.x) >> 5;
    if (wid >= NN) return;
    int lane = threadIdx.x & 31;
    int h = lane & 7;
    int beg = g_off[wid], end = g_off[wid + 1];
    float ald_h = g_ald[wid * HEADS + h];

    // Pass A: max
    float m = -1e30f;
    for (int i = beg + (lane >> 3); i < end; i += 4) {
        int s = g_csr_src[i];
        float ev = g_als[s * HEADS + h] + ald_h;
        ev = ev > 0.f ? ev : 0.2f * ev;
        m = fmaxf(m, ev);
    }
    m = fmaxf(m, __shfl_xor_sync(0xffffffffu, m, 8));
    m = fmaxf(m, __shfl_xor_sync(0xffffffffu, m, 16));
    // Pass A: denom
    float ssum = 0.f;
    for (int i = beg + (lane >> 3); i < end; i += 4) {
        int s = g_csr_src[i];
        float ev = g_als[s * HEADS + h] + ald_h;
        ev = ev > 0.f ? ev : 0.2f * ev;
        ssum += expf(ev - m);
    }
    ssum += __shfl_xor_sync(0xffffffffu, ssum, 8);
    ssum += __shfl_xor_sync(0xffffffffu, ssum, 16);
    float inv = 1.f / (ssum + 1e-16f);

    // Pass B: gather + accumulate
    float acc[8] = {0.f, 0.f, 0.f, 0.f, 0.f, 0.f, 0.f, 0.f};
    for (int i = beg; i < end; i++) {
        int s = g_csr_src[i];
        float ev = g_als[s * HEADS + h] + ald_h;
        ev = ev > 0.f ? ev : 0.2f * ev;
        float alpha = expf(ev - m) * inv;       // lane hh holds alpha for head hh
        const float* f = feat + (size_t)s * 256;
#pragma unroll
        for (int hh = 0; hh < 8; hh++) {
            float a = __shfl_sync(0xffffffffu, alpha, hh);
            acc[hh] += a * f[hh * 32 + lane];
        }
    }
    float* o = out + (size_t)wid * 256;
#pragma unroll
    for (int hh = 0; hh < 8; hh++) o[hh * 32 + lane] = acc[hh];
}

// ---------------- fused aggregation (layer 2, C=128, mean over heads) ------
__global__ void __launch_bounds__(256) agg_big_kernel(const float* __restrict__ feat,
                                                      float* __restrict__ out) {
    int wid = (blockIdx.x * blockDim.x + threadIdx.x) >> 5;
    if (wid >= NN) return;
    int lane = threadIdx.x & 31;
    int h = lane & 7;
    int beg = g_off[wid], end = g_off[wid + 1];
    float ald_h = g_ald[wid * HEADS + h];

    float m = -1e30f;
    for (int i = beg + (lane >> 3); i < end; i += 4) {
        int s = g_csr_src[i];
        float ev = g_als[s * HEADS + h] + ald_h;
        ev = ev > 0.f ? ev : 0.2f * ev;
        m = fmaxf(m, ev);
    }
    m = fmaxf(m, __shfl_xor_sync(0xffffffffu, m, 8));
    m = fmaxf(m, __shfl_xor_sync(0xffffffffu, m, 16));
    float ssum = 0.f;
    for (int i = beg + (lane >> 3); i < end; i += 4) {
        int s = g_csr_src[i];
        float ev = g_als[s * HEADS + h] + ald_h;
        ev = ev > 0.f ? ev : 0.2f * ev;
        ssum += expf(ev - m);
    }
    ssum += __shfl_xor_sync(0xffffffffu, ssum, 8);
    ssum += __shfl_xor_sync(0xffffffffu, ssum, 16);
    float inv = 0.125f / (ssum + 1e-16f);       // fold mean-over-heads

    float acc[4] = {0.f, 0.f, 0.f, 0.f};
    for (int i = beg; i < end; i++) {
        int s = g_csr_src[i];
        float ev = g_als[s * HEADS + h] + ald_h;
        ev = ev > 0.f ? ev : 0.2f * ev;
        float alpha = expf(ev - m) * inv;
        const float* f = feat + (size_t)s * 1024;
#pragma unroll
        for (int hh = 0; hh < 8; hh++) {
            float a = __shfl_sync(0xffffffffu, alpha, hh);
            const float* fh = f + hh * 128;
#pragma unroll
            for (int ch = 0; ch < 4; ch++)
                acc[ch] += a * fh[ch * 32 + lane];
        }
    }
    float* o = out + (size_t)wid * 128;
#pragma unroll
    for (int ch = 0; ch < 4; ch++) o[ch * 32 + lane] = acc[ch];
}

// ---------------- finalize layers 0/1: +bias, LN, +sig*res, ELU ------------
__global__ void finalize01_kernel(const float* __restrict__ bias,
                                  const float* __restrict__ lng, const float* __restrict__ lnb,
                                  const float* __restrict__ res, const float* __restrict__ rb,
                                  const float* __restrict__ rw, float* __restrict__ out) {
    int n = blockIdx.x, t = threadIdx.x;   // 256 threads
    float g = g_accb[(size_t)n * 256 + t] + bias[t];
    float s1 = g, s2 = g * g;
#pragma unroll
    for (int o = 16; o; o >>= 1) {
        s1 += __shfl_down_sync(0xffffffffu, s1, o);
        s2 += __shfl_down_sync(0xffffffffu, s2, o);
    }
    __shared__ float sh1[8], sh2[8];
    __shared__ float mu_s, rs_s;
    int w = t >> 5, l = t & 31;
    if (l == 0) { sh1[w] = s1; sh2[w] = s2; }
    __syncthreads();
    if (t == 0) {
        float a = 0.f, b = 0.f;
#pragma unroll
        for (int i = 0; i < 8; i++) { a += sh1[i]; b += sh2[i]; }
        float mu = a * (1.f / 256.f);
        float var = b * (1.f / 256.f) - mu * mu;
        mu_s = mu;
        rs_s = rsqrtf(var + 1e-5f);
    }
    __syncthreads();
    float y = (g - mu_s) * rs_s * lng[t] + lnb[t];
    float sig = 1.f / (1.f + expf(-rw[0]));
    float r = res[(size_t)n * 256 + t];
    if (rb) r += rb[t];
    float z = y + sig * r;
    out[(size_t)n * 256 + t] = z > 0.f ? z : expm1f(z);   // elu
}

// ---------------- finalize layer 2: +bias, LN, +sig*res (no elu) -----------
__global__ void finalize2_kernel(const float* __restrict__ bias,
                                 const float* __restrict__ lng, const float* __restrict__ lnb,
                                 const float* __restrict__ res, const float* __restrict__ rb,
                                 const float* __restrict__ rw, float* __restrict__ out) {
    int n = blockIdx.x, t = threadIdx.x;   // 128 threads
    float g = g_accb[(size_t)n * 128 + t] + bias[t];
    float s1 = g, s2 = g * g;
#pragma unroll
    for (int o = 16; o; o >>= 1) {
        s1 += __shfl_down_sync(0xffffffffu, s1, o);
        s2 += __shfl_down_sync(0xffffffffu, s2, o);
    }
    __shared__ float sh1[4], sh2[4];
    __shared__ float mu_s, rs_s;
    int w = t >> 5, l = t & 31;
    if (l == 0) { sh1[w] = s1; sh2[w] = s2; }
    __syncthreads();
    if (t == 0) {
        float a = 0.f, b = 0.f;
#pragma unroll
        for (int i = 0; i < 4; i++) { a += sh1[i]; b += sh2[i]; }
        float mu = a * (1.f / 128.f);
        float var = b * (1.f / 128.f) - mu * mu;
        mu_s = mu;
        rs_s = rsqrtf(var + 1e-5f);
    }
    __syncthreads();
    float y = (g - mu_s) * rs_s * lng[t] + lnb[t];
    float sig = 1.f / (1.f + expf(-rw[0]));
    float r = res[(size_t)n * 128 + t] + rb[t];
    out[(size_t)n * 128 + t] = y + sig * r;
}

// ---------------------------------------------------------------------------
extern "C" void kernel_launch(void* const* d_in, const int* in_sizes, int n_in,
                              void* d_out, int out_size) {
    const float* x   = (const float*)d_in[0];
    const void*  ei  = d_in[1];                   // int32 or int64, detected on device
    const float* W0  = (const float*)d_in[2];
    const float* b0  = (const float*)d_in[3];
    const float* as0 = (const float*)d_in[4];
    const float* ad0 = (const float*)d_in[5];
    const float* lng0= (const float*)d_in[6];
    const float* lnb0= (const float*)d_in[7];
    const float* rW0 = (const float*)d_in[8];
    const float* rb0 = (const float*)d_in[9];
    const float* rw0 = (const float*)d_in[10];
    const float* W1  = (const float*)d_in[11];
    const float* b1  = (const float*)d_in[12];
    const float* as1 = (const float*)d_in[13];
    const float* ad1 = (const float*)d_in[14];
    const float* lng1= (const float*)d_in[15];
    const float* lnb1= (const float*)d_in[16];
    const float* rw1 = (const float*)d_in[17];
    const float* W2  = (const float*)d_in[18];
    const float* b2  = (const float*)d_in[19];
    const float* as2 = (const float*)d_in[20];
    const float* ad2 = (const float*)d_in[21];
    const float* lng2= (const float*)d_in[22];
    const float* lnb2= (const float*)d_in[23];
    const float* rW2 = (const float*)d_in[24];
    const float* rb2 = (const float*)d_in[25];
    const float* rw2 = (const float*)d_in[26];

    float *feat, *act0, *act1, *res, *accb;
    __nv_bfloat16 *Ah, *Al, *Bh, *Bl;
    cudaGetSymbolAddress((void**)&feat, g_feat);
    cudaGetSymbolAddress((void**)&act0, g_act0);
    cudaGetSymbolAddress((void**)&act1, g_act1);
    cudaGetSymbolAddress((void**)&res,  g_resb);
    cudaGetSymbolAddress((void**)&accb, g_accb);
    cudaGetSymbolAddress((void**)&Ah, g_Ah);
    cudaGetSymbolAddress((void**)&Al, g_Al);
    cudaGetSymbolAddress((void**)&Bh, g_Bh);
    cudaGetSymbolAddress((void**)&Bl, g_Bl);

    const int TB = 256;
    detect_kernel<<<1, 256>>>((const int*)ei);
    build_edges_kernel<<<(ET + TB - 1) / TB, TB>>>(ei);
    hist_kernel<<<(ET + TB - 1) / TB, TB>>>();
    scan_kernel<<<1, 1024>>>();
    scatter_kernel<<<(ET + TB - 1) / TB, TB>>>();

    int alBlocks  = (NN * HEADS + TB - 1) / TB;
    int aggBlocks = (NN * 32 + TB - 1) / TB;
    const int MROWS = MP / 128;   // 157

    auto splitN = [&](const float* src, __nv_bfloat16* h, __nv_bfloat16* l,
                      int realE, int totE) {
        split_kernel<<<(totE / 4 + TB - 1) / TB, TB>>>(src, h, l, realE, totE);
    };

    // ---------------- layer 0 ----------------
    splitN(x, Ah, Al, NN * 64, MP * 64);
    splitN(W0, Bh, Bl, 64 * 256, 64 * 256);
    gemm_tc_kernel<<<dim3(2, MROWS), 256>>>(Ah, Al, Bh, Bl, feat, 256, 64);
    splitN(rW0, Bh, Bl, 64 * 256, 64 * 256);
    gemm_tc_kernel<<<dim3(2, MROWS), 256>>>(Ah, Al, Bh, Bl, res, 256, 64);
    al_kernel<<<alBlocks, TB>>>(as0, ad0, 32);
    agg_small_kernel<<<aggBlocks, TB>>>(feat, accb);
    finalize01_kernel<<<NN, 256>>>(b0, lng0, lnb0, res, rb0, rw0, act0);

    // ---------------- layer 1 ----------------
    splitN(act0, Ah, Al, NN * 256, MP * 256);
    splitN(W1, Bh, Bl, 256 * 256, 256 * 256);
    gemm_tc_kernel<<<dim3(2, MROWS), 256>>>(Ah, Al, Bh, Bl, feat, 256, 256);
    al_kernel<<<alBlocks, TB>>>(as1, ad1, 32);
    agg_small_kernel<<<aggBlocks, TB>>>(feat, accb);
    finalize01_kernel<<<NN, 256>>>(b1, lng1, lnb1, act0, nullptr, rw1, act1);

    // ---------------- layer 2 ----------------
    splitN(act1, Ah, Al, NN * 256, MP * 256);
    splitN(W2, Bh, Bl, 256 * 1024, 256 * 1024);
    gemm_tc_kernel<<<dim3(8, MROWS), 256>>>(Ah, Al, Bh, Bl, feat, 1024, 256);
    splitN(rW2, Bh, Bl, 256 * 128, 256 * 128);
    gemm_tc_kernel<<<dim3(1, MROWS), 256>>>(Ah, Al, Bh, Bl, res, 128, 256);
    al_kernel<<<alBlocks, TB>>>(as2, ad2, 128);
    agg_big_kernel<<<aggBlocks, TB>>>(feat, accb);
    finalize2_kernel<<<NN, 128>>>(b2, lng2, lnb2, res, rb2, rw2, (float*)d_out);
}